// round 6
// baseline (speedup 1.0000x reference)
#include <cuda_runtime.h>
#include <cstdint>

#define HDIM 128
#define MAXN 65536
#define MAXE 2200000

// Scratch (allocation-free rule). Never referenced from host code.
__device__ __align__(16) float g_buf0[(size_t)MAXN * HDIM]; // hs (unscaled gemm out)
__device__ __align__(16) float g_buf1[(size_t)MAXN * HDIM]; // layer-1 activations
__device__ float g_dis[MAXN];
__device__ int   g_deg2[MAXN];      // in-degree (edges only)
__device__ int   g_cur[MAXN];       // fill cursor
__device__ int   g_off[MAXN + 1];   // CSR offsets (by dst)
__device__ int   g_csr[MAXE];       // CSR: src per edge slot
__device__ int   g_bsum[64];
__device__ int   g_bpre[64];
__device__ int   g_is64;

// ---------------- setup0: zero deg/cur + dtype probe (block 0, warp 0) ------
__global__ void k_setup0(const void* __restrict__ ei, int E, int N) {
    int i = blockIdx.x * blockDim.x + threadIdx.x;
    if (i < N) { g_deg2[i] = 0; g_cur[i] = 0; }
    if (blockIdx.x == 0 && threadIdx.x < 32) {
        int lane = threadIdx.x;
        const long long* p = (const long long*)ei;
        int n = E < 32 ? E : 32;
        long long v = (lane < n) ? p[lane] : 0;
        bool ok = (v >= 0 && v < (long long)N);
        unsigned m = __ballot_sync(0xffffffffu, ok);
        if (lane == 0) g_is64 = (m == 0xffffffffu) ? 1 : 0;
    }
}

__device__ __forceinline__ int load_idx(const void* __restrict__ ei, size_t pos) {
    return g_is64 ? (int)((const long long*)ei)[pos]
                  : ((const int*)ei)[pos];
}

// ---------------- degree count ----------------
__global__ void k_count(const void* __restrict__ ei, int E, int N) {
    int e = blockIdx.x * blockDim.x + threadIdx.x;
    if (e >= E) return;
    int d = load_idx(ei, (size_t)E + e);
    if ((unsigned)d < (unsigned)N) atomicAdd(&g_deg2[d], 1);
}

// ---------------- scan (also computes g_dis) ----------------
__global__ __launch_bounds__(256) void k_scan1(int N) {
    __shared__ int ssum[256];
    int base = blockIdx.x * 1024 + threadIdx.x * 4;
    int v0 = 0, v1 = 0, v2 = 0, v3 = 0;
    if (base + 0 < N) v0 = g_deg2[base + 0];
    if (base + 1 < N) v1 = g_deg2[base + 1];
    if (base + 2 < N) v2 = g_deg2[base + 2];
    if (base + 3 < N) v3 = g_deg2[base + 3];
    // fused normalization: dis = rsqrt(1 + indeg)
    if (base + 0 < N) g_dis[base + 0] = rsqrtf((float)(1 + v0));
    if (base + 1 < N) g_dis[base + 1] = rsqrtf((float)(1 + v1));
    if (base + 2 < N) g_dis[base + 2] = rsqrtf((float)(1 + v2));
    if (base + 3 < N) g_dis[base + 3] = rsqrtf((float)(1 + v3));
    int t = v0 + v1 + v2 + v3;
    ssum[threadIdx.x] = t;
    __syncthreads();
    for (int d = 1; d < 256; d <<= 1) {
        int x = (threadIdx.x >= d) ? ssum[threadIdx.x - d] : 0;
        __syncthreads();
        ssum[threadIdx.x] += x;
        __syncthreads();
    }
    int excl = ssum[threadIdx.x] - t;
    if (base + 0 < N) g_off[base + 0] = excl;
    if (base + 1 < N) g_off[base + 1] = excl + v0;
    if (base + 2 < N) g_off[base + 2] = excl + v0 + v1;
    if (base + 3 < N) g_off[base + 3] = excl + v0 + v1 + v2;
    if (threadIdx.x == 255) g_bsum[blockIdx.x] = ssum[255];
}

__global__ void k_scan2(int nb, int N, int E) {
    __shared__ int s[64];
    int i = threadIdx.x;
    int v = (i < nb) ? g_bsum[i] : 0;
    s[i] = v;
    __syncthreads();
    for (int d = 1; d < 64; d <<= 1) {
        int x = (i >= d) ? s[i - d] : 0;
        __syncthreads();
        s[i] += x;
        __syncthreads();
    }
    if (i < nb) g_bpre[i] = s[i] - v;
    if (i == 0) g_off[N] = E;
}

__global__ void k_scan3(int N) {
    int i = blockIdx.x * blockDim.x + threadIdx.x;
    if (i < N) g_off[i] += g_bpre[i >> 10];
}

// ---------------- CSR fill ----------------
__global__ void k_fill(const void* __restrict__ ei, int E, int N) {
    int e = blockIdx.x * blockDim.x + threadIdx.x;
    if (e >= E) return;
    int s = load_idx(ei, e);
    int d = load_idx(ei, (size_t)E + e);
    if ((unsigned)d >= (unsigned)N) return;
    if ((unsigned)s >= (unsigned)N) s = 0;
    int pos = atomicAdd(&g_cur[d], 1);
    g_csr[g_off[d] + pos] = s;
}

// ---------------- GEMM: hs = X @ W -> g_buf0 (NO dis scaling) ----------------
// srcSel: 0 = external X, 1 = g_buf1.
__global__ __launch_bounds__(256) void k_gemm(
    const float* __restrict__ Xext, const float* __restrict__ W,
    int N, int srcSel)
{
    __shared__ float sA[64][HDIM];
    const float* __restrict__ X = srcSel ? g_buf1 : Xext;

    int tx = threadIdx.x & 31;
    int ty = threadIdx.x >> 5;
    int rowBase = blockIdx.x * 64;

    for (int t = threadIdx.x; t < 64 * (HDIM / 4); t += 256) {
        int r  = t >> 5;
        int c4 = t & 31;
        int row = rowBase + r;
        float4 v = make_float4(0.f, 0.f, 0.f, 0.f);
        if (row < N) v = *(const float4*)(X + (size_t)row * HDIM + c4 * 4);
        *(float4*)(&sA[r][c4 * 4]) = v;
    }
    __syncthreads();

    float acc[8][4];
    #pragma unroll
    for (int i = 0; i < 8; i++)
        #pragma unroll
        for (int c = 0; c < 4; c++) acc[i][c] = 0.f;

    #pragma unroll 4
    for (int k = 0; k < HDIM; k++) {
        float4 w = __ldg((const float4*)(W + (size_t)k * HDIM + tx * 4));
        #pragma unroll
        for (int i = 0; i < 8; i++) {
            float a = sA[ty * 8 + i][k];
            acc[i][0] = fmaf(a, w.x, acc[i][0]);
            acc[i][1] = fmaf(a, w.y, acc[i][1]);
            acc[i][2] = fmaf(a, w.z, acc[i][2]);
            acc[i][3] = fmaf(a, w.w, acc[i][3]);
        }
    }

    #pragma unroll
    for (int i = 0; i < 8; i++) {
        int row = rowBase + ty * 8 + i;
        if (row < N) {
            float4 v = make_float4(acc[i][0], acc[i][1], acc[i][2], acc[i][3]);
            *(float4*)(g_buf0 + (size_t)row * HDIM + tx * 4) = v;
        }
    }
}

// ---------------- gather + finalize (dis applied per-src here) ----------------
// out[node] = relu(dis[node] * (dis[node]*hs[node] + sum_src dis[src]*hs[src]) + b)
__global__ __launch_bounds__(256) void k_gather(
    float* __restrict__ out_ext, const float* __restrict__ bias,
    int N, int useExt)
{
    int node = blockIdx.x * 8 + (threadIdx.x >> 5);
    if (node >= N) return;
    int lane = threadIdx.x & 31;
    const float* __restrict__ hs = g_buf0;

    float dn = g_dis[node];
    float4 a0 = *(const float4*)(hs + (size_t)node * HDIM + lane * 4);
    float4 acc = make_float4(a0.x * dn, a0.y * dn, a0.z * dn, a0.w * dn);

    int beg = g_off[node], end = g_off[node + 1];
    for (int base = beg; base < end; base += 32) {
        int n = end - base; if (n > 32) n = 32;
        int eid = (lane < n) ? g_csr[base + lane] : 0;
        float fd = (lane < n) ? g_dis[eid] : 0.f;
        #pragma unroll 8
        for (int j = 0; j < n; j++) {
            int   s  = __shfl_sync(0xffffffffu, eid, j);
            float ds = __shfl_sync(0xffffffffu, fd,  j);
            float4 v = __ldg((const float4*)(hs + (size_t)s * HDIM + lane * 4));
            acc.x = fmaf(v.x, ds, acc.x);
            acc.y = fmaf(v.y, ds, acc.y);
            acc.z = fmaf(v.z, ds, acc.z);
            acc.w = fmaf(v.w, ds, acc.w);
        }
    }

    float4 bb = __ldg((const float4*)(bias + lane * 4));
    float4 r;
    r.x = fmaxf(fmaf(dn, acc.x, bb.x), 0.f);
    r.y = fmaxf(fmaf(dn, acc.y, bb.y), 0.f);
    r.z = fmaxf(fmaf(dn, acc.z, bb.z), 0.f);
    r.w = fmaxf(fmaf(dn, acc.w, bb.w), 0.f);

    float* __restrict__ out = useExt ? out_ext : g_buf1;
    *(float4*)(out + (size_t)node * HDIM + lane * 4) = r;
}

extern "C" void kernel_launch(void* const* d_in, const int* in_sizes, int n_in,
                              void* d_out, int out_size)
{
    const float* x  = (const float*)d_in[0];
    const void*  ei = d_in[1];
    const float* W1 = (const float*)d_in[2];
    const float* b1 = (const float*)d_in[3];
    const float* W2 = (const float*)d_in[4];
    const float* b2 = (const float*)d_in[5];

    int H = in_sizes[3];
    int D = in_sizes[2] / H;
    int N = in_sizes[0] / D;
    int E = in_sizes[1] / 2;
    (void)D; (void)n_in; (void)out_size;

    int nb    = (N + 1023) / 1024;
    int eb    = (E + 255) / 256;
    int nb256 = (N + 255) / 256;

    // Side streams + events, created once on the (non-captured) correctness
    // call; reused identically every call (deterministic work).
    static cudaStream_t sA = nullptr, sB = nullptr;
    static cudaEvent_t  evR = nullptr, evA = nullptr, evB = nullptr;
    if (sA == nullptr) {
        cudaStreamCreateWithFlags(&sA, cudaStreamNonBlocking);
        cudaStreamCreateWithFlags(&sB, cudaStreamNonBlocking);
        cudaEventCreateWithFlags(&evR, cudaEventDisableTiming);
        cudaEventCreateWithFlags(&evA, cudaEventDisableTiming);
        cudaEventCreateWithFlags(&evB, cudaEventDisableTiming);
    }

    int gemmBlocks = (N + 63) / 64;
    int gathBlocks = (N + 7) / 8;

    // root: zero + dtype probe
    k_setup0<<<nb256, 256>>>(ei, E, N);
    cudaEventRecord(evR, 0);
    cudaStreamWaitEvent(sA, evR, 0);
    cudaStreamWaitEvent(sB, evR, 0);

    // branch A: degree -> scan(+dis) -> CSR fill
    k_count<<<eb, 256, 0, sA>>>(ei, E, N);
    k_scan1<<<nb, 256, 0, sA>>>(N);
    k_scan2<<<1, 64, 0, sA>>>(nb, N, E);
    k_scan3<<<nb256, 256, 0, sA>>>(N);
    k_fill<<<eb, 256, 0, sA>>>(ei, E, N);
    cudaEventRecord(evA, sA);

    // branch B: layer-1 GEMM (independent of normalization now)
    k_gemm<<<gemmBlocks, 256, 0, sB>>>(x, W1, N, 0);
    cudaEventRecord(evB, sB);

    // join
    cudaStreamWaitEvent(0, evA, 0);
    cudaStreamWaitEvent(0, evB, 0);

    // layer 1 aggregate -> buf1 ; layer 2
    k_gather<<<gathBlocks, 256>>>(nullptr, b1, N, 0);
    k_gemm<<<gemmBlocks, 256>>>(nullptr, W2, N, 1);
    k_gather<<<gathBlocks, 256>>>((float*)d_out, b2, N, 1);
}

// round 9
// speedup vs baseline: 1.2324x; 1.2324x over previous
#include <cuda_runtime.h>
#include <cuda_fp16.h>
#include <cstdint>

#define HDIM 128
#define MAXN 65536
#define MAXE 2200000

// Scratch (allocation-free rule). Never referenced from host code.
__device__ __align__(16) __half2 g_hs[(size_t)MAXN * 64];    // hsd (scaled gemm out, fp16)
__device__ __align__(16) float   g_act[(size_t)MAXN * HDIM]; // layer-1 activations (fp32)
__device__ float g_dis[MAXN];
__device__ int   g_deg2[MAXN];      // in-degree (edges only)
__device__ int   g_cur[MAXN];       // fill cursor
__device__ int   g_off[MAXN + 1];   // CSR offsets (by dst)
__device__ int   g_csr[MAXE];       // CSR: src per edge slot
__device__ int   g_bsum[64];
__device__ int   g_is64;

__device__ __forceinline__ unsigned h2_to_u32(__half2 h) {
    return *reinterpret_cast<unsigned*>(&h);
}
__device__ __forceinline__ __half2 u32_to_h2(unsigned u) {
    return *reinterpret_cast<__half2*>(&u);
}

// ---------------- setup0: zero deg/cur + dtype probe ----------------
__global__ void k_setup0(const void* __restrict__ ei, int E, int N) {
    int i = blockIdx.x * blockDim.x + threadIdx.x;
    if (i < N) { g_deg2[i] = 0; g_cur[i] = 0; }
    if (blockIdx.x == 0 && threadIdx.x < 32) {
        int lane = threadIdx.x;
        const long long* p = (const long long*)ei;
        int n = E < 32 ? E : 32;
        long long v = (lane < n) ? p[lane] : 0;
        bool ok = (v >= 0 && v < (long long)N);
        unsigned m = __ballot_sync(0xffffffffu, ok);
        if (lane == 0) g_is64 = (m == 0xffffffffu) ? 1 : 0;
    }
}

__device__ __forceinline__ int load_idx(const void* __restrict__ ei, size_t pos) {
    return g_is64 ? (int)((const long long*)ei)[pos]
                  : ((const int*)ei)[pos];
}

// ---------------- degree count ----------------
__global__ void k_count(const void* __restrict__ ei, int E, int N) {
    int e = blockIdx.x * blockDim.x + threadIdx.x;
    if (e >= E) return;
    int d = load_idx(ei, (size_t)E + e);
    if ((unsigned)d < (unsigned)N) atomicAdd(&g_deg2[d], 1);
}

// ---------------- scan1: per-1024 partial offsets, block sums, g_dis --------
__global__ __launch_bounds__(256) void k_scan1(int N) {
    __shared__ int ssum[256];
    int base = blockIdx.x * 1024 + threadIdx.x * 4;
    int v0 = 0, v1 = 0, v2 = 0, v3 = 0;
    if (base + 0 < N) v0 = g_deg2[base + 0];
    if (base + 1 < N) v1 = g_deg2[base + 1];
    if (base + 2 < N) v2 = g_deg2[base + 2];
    if (base + 3 < N) v3 = g_deg2[base + 3];
    if (base + 0 < N) g_dis[base + 0] = rsqrtf((float)(1 + v0));
    if (base + 1 < N) g_dis[base + 1] = rsqrtf((float)(1 + v1));
    if (base + 2 < N) g_dis[base + 2] = rsqrtf((float)(1 + v2));
    if (base + 3 < N) g_dis[base + 3] = rsqrtf((float)(1 + v3));
    int t = v0 + v1 + v2 + v3;
    ssum[threadIdx.x] = t;
    __syncthreads();
    for (int d = 1; d < 256; d <<= 1) {
        int x = (threadIdx.x >= d) ? ssum[threadIdx.x - d] : 0;
        __syncthreads();
        ssum[threadIdx.x] += x;
        __syncthreads();
    }
    int excl = ssum[threadIdx.x] - t;
    if (base + 0 < N) g_off[base + 0] = excl;
    if (base + 1 < N) g_off[base + 1] = excl + v0;
    if (base + 2 < N) g_off[base + 2] = excl + v0 + v1;
    if (base + 3 < N) g_off[base + 3] = excl + v0 + v1 + v2;
    if (threadIdx.x == 255) g_bsum[blockIdx.x] = ssum[255];
}

// ---------------- scan23: add block-group prefix (fused scan2+scan3) --------
__global__ __launch_bounds__(256) void k_scan23(int N, int E) {
    __shared__ int spre;
    int grp = blockIdx.x >> 2;           // 1024-group index
    if (threadIdx.x < 32) {
        int lane = threadIdx.x;
        int s = 0;
        for (int j = lane; j < grp; j += 32) s += g_bsum[j];
        #pragma unroll
        for (int o = 16; o; o >>= 1) s += __shfl_xor_sync(0xffffffffu, s, o);
        if (lane == 0) spre = s;
    }
    __syncthreads();
    int i = blockIdx.x * 256 + threadIdx.x;
    if (i < N) g_off[i] += spre;
    if (i == 0) g_off[N] = E;
}

// ---------------- CSR fill ----------------
__global__ void k_fill(const void* __restrict__ ei, int E, int N) {
    int e = blockIdx.x * blockDim.x + threadIdx.x;
    if (e >= E) return;
    int s = load_idx(ei, e);
    int d = load_idx(ei, (size_t)E + e);
    if ((unsigned)d >= (unsigned)N) return;
    if ((unsigned)s >= (unsigned)N) s = 0;
    int pos = atomicAdd(&g_cur[d], 1);
    g_csr[g_off[d] + pos] = s;
}

// ---------------- GEMM: hsd = (X @ W)*dis[row] -> g_hs (fp16) ----------------
// srcSel: 0 = external X, 1 = g_act.
__global__ __launch_bounds__(256) void k_gemm(
    const float* __restrict__ Xext, const float* __restrict__ W,
    int N, int srcSel)
{
    __shared__ float sA[64][HDIM];
    const float* __restrict__ X = srcSel ? g_act : Xext;

    int tx = threadIdx.x & 31;
    int ty = threadIdx.x >> 5;
    int rowBase = blockIdx.x * 64;

    for (int t = threadIdx.x; t < 64 * (HDIM / 4); t += 256) {
        int r  = t >> 5;
        int c4 = t & 31;
        int row = rowBase + r;
        float4 v = make_float4(0.f, 0.f, 0.f, 0.f);
        if (row < N) v = *(const float4*)(X + (size_t)row * HDIM + c4 * 4);
        *(float4*)(&sA[r][c4 * 4]) = v;
    }
    __syncthreads();

    float acc[8][4];
    #pragma unroll
    for (int i = 0; i < 8; i++)
        #pragma unroll
        for (int c = 0; c < 4; c++) acc[i][c] = 0.f;

    #pragma unroll 4
    for (int k = 0; k < HDIM; k++) {
        float4 w = __ldg((const float4*)(W + (size_t)k * HDIM + tx * 4));
        #pragma unroll
        for (int i = 0; i < 8; i++) {
            float a = sA[ty * 8 + i][k];
            acc[i][0] = fmaf(a, w.x, acc[i][0]);
            acc[i][1] = fmaf(a, w.y, acc[i][1]);
            acc[i][2] = fmaf(a, w.z, acc[i][2]);
            acc[i][3] = fmaf(a, w.w, acc[i][3]);
        }
    }

    #pragma unroll
    for (int i = 0; i < 8; i++) {
        int row = rowBase + ty * 8 + i;
        if (row < N) {
            float s = g_dis[row];
            __half2 h0 = __float22half2_rn(make_float2(acc[i][0] * s, acc[i][1] * s));
            __half2 h1 = __float22half2_rn(make_float2(acc[i][2] * s, acc[i][3] * s));
            *(uint2*)(g_hs + (size_t)row * 64 + tx * 2)
                = make_uint2(h2_to_u32(h0), h2_to_u32(h1));
        }
    }
}

// ---------------- gather + finalize ----------------
// acc = hsd[node] + sum_src hsd[src]  (fp32 accum over fp16 rows)
// out[node] = relu(dis[node]*acc + b)
__global__ __launch_bounds__(256) void k_gather(
    float* __restrict__ out_ext, const float* __restrict__ bias,
    int N, int useExt)
{
    int node = blockIdx.x * 8 + (threadIdx.x >> 5);
    if (node >= N) return;
    int lane = threadIdx.x & 31;

    // self term
    uint2 u = *(const uint2*)(g_hs + (size_t)node * 64 + lane * 2);
    float2 f0 = __half22float2(u32_to_h2(u.x));
    float2 f1 = __half22float2(u32_to_h2(u.y));
    float4 acc = make_float4(f0.x, f0.y, f1.x, f1.y);

    int beg = g_off[node], end = g_off[node + 1];
    for (int base = beg; base < end; base += 32) {
        int n = end - base; if (n > 32) n = 32;
        int eid = (lane < n) ? g_csr[base + lane] : 0;
        #pragma unroll 8
        for (int j = 0; j < n; j++) {
            int s = __shfl_sync(0xffffffffu, eid, j);
            uint2 v = __ldg((const uint2*)(g_hs + (size_t)s * 64 + lane * 2));
            float2 a = __half22float2(u32_to_h2(v.x));
            float2 b = __half22float2(u32_to_h2(v.y));
            acc.x += a.x; acc.y += a.y; acc.z += b.x; acc.w += b.y;
        }
    }

    float dn = g_dis[node];
    float4 bb = __ldg((const float4*)(bias + lane * 4));
    float4 r;
    r.x = fmaxf(fmaf(dn, acc.x, bb.x), 0.f);
    r.y = fmaxf(fmaf(dn, acc.y, bb.y), 0.f);
    r.z = fmaxf(fmaf(dn, acc.z, bb.z), 0.f);
    r.w = fmaxf(fmaf(dn, acc.w, bb.w), 0.f);

    float* __restrict__ out = useExt ? out_ext : g_act;
    *(float4*)(out + (size_t)node * HDIM + lane * 4) = r;
}

extern "C" void kernel_launch(void* const* d_in, const int* in_sizes, int n_in,
                              void* d_out, int out_size)
{
    const float* x  = (const float*)d_in[0];
    const void*  ei = d_in[1];
    const float* W1 = (const float*)d_in[2];
    const float* b1 = (const float*)d_in[3];
    const float* W2 = (const float*)d_in[4];
    const float* b2 = (const float*)d_in[5];

    int H = in_sizes[3];
    int D = in_sizes[2] / H;
    int N = in_sizes[0] / D;
    int E = in_sizes[1] / 2;
    (void)D; (void)n_in; (void)out_size;

    int nb    = (N + 1023) / 1024;
    int eb    = (E + 255) / 256;
    int nb256 = (N + 255) / 256;

    int gemmBlocks = (N + 63) / 64;
    int gathBlocks = (N + 7) / 8;

    // setup + CSR build (serial — overlap measured as a regression in R6)
    k_setup0<<<nb256, 256>>>(ei, E, N);
    k_count<<<eb, 256>>>(ei, E, N);
    k_scan1<<<nb, 256>>>(N);
    k_scan23<<<nb256, 256>>>(N, E);
    k_fill<<<eb, 256>>>(ei, E, N);

    // layer 1
    k_gemm<<<gemmBlocks, 256>>>(x, W1, N, 0);
    k_gather<<<gathBlocks, 256>>>(nullptr, b1, N, 0);

    // layer 2
    k_gemm<<<gemmBlocks, 256>>>(nullptr, W2, N, 1);
    k_gather<<<gathBlocks, 256>>>((float*)d_out, b2, N, 1);
}

// round 11
// speedup vs baseline: 1.5320x; 1.2430x over previous
#include <cuda_runtime.h>
#include <cuda_fp16.h>
#include <cstdint>

#define HDIM 128
#define MAXN 65536
#define MAXE 2200000

// ---------------- scratch (never referenced from host code) ----------------
__device__ __align__(16) __half2 g_hs[(size_t)MAXN * 64];     // hsd (scaled gemm out, fp16)
__device__ __align__(16) float   g_act[(size_t)MAXN * HDIM];  // layer-1 activations (fp32)
__device__ __align__(16) __half2 g_wf16[2][HDIM * 64];        // W fp16 [layer][k*64 + n2] ([k][n])
__device__ float g_dis[MAXN];
__device__ int   g_deg2[MAXN];
__device__ int   g_cur[MAXN];
__device__ int   g_off[MAXN + 1];
__device__ int   g_csr[MAXE];
__device__ int   g_bsum[64];
__device__ int   g_is64;

// ---------------- small helpers ----------------
__device__ __forceinline__ unsigned h2_to_u32(__half2 h) {
    return *reinterpret_cast<unsigned*>(&h);
}
__device__ __forceinline__ __half2 u32_to_h2(unsigned u) {
    return *reinterpret_cast<__half2*>(&u);
}
__device__ __forceinline__ uint32_t smem_u32(const void* p) {
    uint32_t a;
    asm("{ .reg .u64 t; cvta.to.shared.u64 t, %1; cvt.u32.u64 %0, t; }"
        : "=r"(a) : "l"(p));
    return a;
}

// ---------------- setup0: zero deg/cur + dtype probe ----------------
__global__ void k_setup0(const void* __restrict__ ei, int E, int N) {
    int i = blockIdx.x * blockDim.x + threadIdx.x;
    if (i < N) { g_deg2[i] = 0; g_cur[i] = 0; }
    if (blockIdx.x == 0 && threadIdx.x < 32) {
        int lane = threadIdx.x;
        const long long* p = (const long long*)ei;
        int n = E < 32 ? E : 32;
        long long v = (lane < n) ? p[lane] : 0;
        bool ok = (v >= 0 && v < (long long)N);
        unsigned m = __ballot_sync(0xffffffffu, ok);
        if (lane == 0) g_is64 = (m == 0xffffffffu) ? 1 : 0;
    }
}

__device__ __forceinline__ int load_idx(const void* __restrict__ ei, size_t pos) {
    return g_is64 ? (int)((const long long*)ei)[pos]
                  : ((const int*)ei)[pos];
}

// ---------------- W fp16 conversion, [k][n] layout kept ----------------
__global__ void k_convW(const float* __restrict__ W1, const float* __restrict__ W2) {
    int idx = blockIdx.x * blockDim.x + threadIdx.x;   // 2 * 128 * 64
    if (idx >= 2 * HDIM * 64) return;
    int l  = idx >> 13;
    int r  = idx & 8191;
    int k  = r >> 6;
    int n2 = r & 63;
    const float* W = l ? W2 : W1;
    float a = W[(size_t)k * HDIM + 2 * n2];
    float b = W[(size_t)k * HDIM + 2 * n2 + 1];
    g_wf16[l][k * 64 + n2] = __float22half2_rn(make_float2(a, b));
}

// ---------------- degree count ----------------
__global__ void k_count(const void* __restrict__ ei, int E, int N) {
    int e = blockIdx.x * blockDim.x + threadIdx.x;
    if (e >= E) return;
    int d = load_idx(ei, (size_t)E + e);
    if ((unsigned)d < (unsigned)N) atomicAdd(&g_deg2[d], 1);
}

// ---------------- scan1 ----------------
__global__ __launch_bounds__(256) void k_scan1(int N) {
    __shared__ int ssum[256];
    int base = blockIdx.x * 1024 + threadIdx.x * 4;
    int v0 = 0, v1 = 0, v2 = 0, v3 = 0;
    if (base + 0 < N) v0 = g_deg2[base + 0];
    if (base + 1 < N) v1 = g_deg2[base + 1];
    if (base + 2 < N) v2 = g_deg2[base + 2];
    if (base + 3 < N) v3 = g_deg2[base + 3];
    if (base + 0 < N) g_dis[base + 0] = rsqrtf((float)(1 + v0));
    if (base + 1 < N) g_dis[base + 1] = rsqrtf((float)(1 + v1));
    if (base + 2 < N) g_dis[base + 2] = rsqrtf((float)(1 + v2));
    if (base + 3 < N) g_dis[base + 3] = rsqrtf((float)(1 + v3));
    int t = v0 + v1 + v2 + v3;
    ssum[threadIdx.x] = t;
    __syncthreads();
    for (int d = 1; d < 256; d <<= 1) {
        int x = (threadIdx.x >= d) ? ssum[threadIdx.x - d] : 0;
        __syncthreads();
        ssum[threadIdx.x] += x;
        __syncthreads();
    }
    int excl = ssum[threadIdx.x] - t;
    if (base + 0 < N) g_off[base + 0] = excl;
    if (base + 1 < N) g_off[base + 1] = excl + v0;
    if (base + 2 < N) g_off[base + 2] = excl + v0 + v1;
    if (base + 3 < N) g_off[base + 3] = excl + v0 + v1 + v2;
    if (threadIdx.x == 255) g_bsum[blockIdx.x] = ssum[255];
}

// ---------------- scan23 (fused) ----------------
__global__ __launch_bounds__(256) void k_scan23(int N, int E) {
    __shared__ int spre;
    int grp = blockIdx.x >> 2;
    if (threadIdx.x < 32) {
        int lane = threadIdx.x;
        int s = 0;
        for (int j = lane; j < grp; j += 32) s += g_bsum[j];
        #pragma unroll
        for (int o = 16; o; o >>= 1) s += __shfl_xor_sync(0xffffffffu, s, o);
        if (lane == 0) spre = s;
    }
    __syncthreads();
    int i = blockIdx.x * 256 + threadIdx.x;
    if (i < N) g_off[i] += spre;
    if (i == 0) g_off[N] = E;
}

// ---------------- CSR fill ----------------
__global__ void k_fill(const void* __restrict__ ei, int E, int N) {
    int e = blockIdx.x * blockDim.x + threadIdx.x;
    if (e >= E) return;
    int s = load_idx(ei, e);
    int d = load_idx(ei, (size_t)E + e);
    if ((unsigned)d >= (unsigned)N) return;
    if ((unsigned)s >= (unsigned)N) s = 0;
    int pos = atomicAdd(&g_cur[d], 1);
    g_csr[g_off[d] + pos] = s;
}

// ================= HMMA GEMM (mma.sync, baseline sm_80 path) =================
// Per block: rows [blockIdx*128, +128) x N=128 x K=128.
// A = X rows (fp32 -> fp16) row-major [m][k]; B = W fp16 row-major [k][n].
// mma.m16n8k16.row.col with ldmatrix (A no-trans, B trans).
#define ASTRIDE 136                     // halves per row (128 + 8 pad, 16B-aligned)
#define SMA_BYTES (128 * ASTRIDE * 2)
#define SM_BYTES  (2 * SMA_BYTES)       // 69632

__device__ __forceinline__ void ldm_x4(uint32_t* r, uint32_t addr) {
    asm volatile("ldmatrix.sync.aligned.m8n8.x4.shared.b16 {%0,%1,%2,%3}, [%4];"
                 : "=r"(r[0]), "=r"(r[1]), "=r"(r[2]), "=r"(r[3]) : "r"(addr));
}
__device__ __forceinline__ void ldm_x4_t(uint32_t* r, uint32_t addr) {
    asm volatile("ldmatrix.sync.aligned.m8n8.x4.trans.shared.b16 {%0,%1,%2,%3}, [%4];"
                 : "=r"(r[0]), "=r"(r[1]), "=r"(r[2]), "=r"(r[3]) : "r"(addr));
}
__device__ __forceinline__ void mma16816(float* c, const uint32_t* a, const uint32_t* b) {
    asm volatile(
        "mma.sync.aligned.m16n8k16.row.col.f32.f16.f16.f32 "
        "{%0,%1,%2,%3}, {%4,%5,%6,%7}, {%8,%9}, {%0,%1,%2,%3};"
        : "+f"(c[0]), "+f"(c[1]), "+f"(c[2]), "+f"(c[3])
        : "r"(a[0]), "r"(a[1]), "r"(a[2]), "r"(a[3]), "r"(b[0]), "r"(b[1]));
}

__global__ __launch_bounds__(256) void k_gemm_mma(
    const float* __restrict__ Xext, int N, int srcSel)
{
    extern __shared__ char smem[];
    uint32_t sbA = smem_u32(smem);
    uint32_t sbB = sbA + SMA_BYTES;
    int tid = threadIdx.x, wid = tid >> 5, lane = tid & 31;
    const float* __restrict__ X = srcSel ? g_act : Xext;
    const __half2* __restrict__ WH = g_wf16[srcSel];
    int rowBase = blockIdx.x * 128;

    // load A (fp32 -> fp16) into padded smem [128][ASTRIDE]
    __half* sA = (__half*)smem;
    for (int idx = tid; idx < 128 * 32; idx += 256) {
        int r = idx >> 5, c4 = idx & 31;
        int row = rowBase + r;
        float4 v = make_float4(0.f, 0.f, 0.f, 0.f);
        if (row < N) v = *(const float4*)(X + (size_t)row * HDIM + c4 * 4);
        unsigned h0 = h2_to_u32(__float22half2_rn(make_float2(v.x, v.y)));
        unsigned h1 = h2_to_u32(__float22half2_rn(make_float2(v.z, v.w)));
        *(uint2*)(sA + r * ASTRIDE + c4 * 4) = make_uint2(h0, h1);
    }
    // load B (pre-converted fp16 [k][n]) into padded smem
    __half* sB = (__half*)(smem + SMA_BYTES);
    for (int idx = tid; idx < 128 * 32; idx += 256) {
        int k = idx >> 5, c4 = idx & 31;
        uint2 v = *(const uint2*)(WH + k * 64 + c4 * 2);
        *(uint2*)(sB + k * ASTRIDE + c4 * 4) = v;
    }
    __syncthreads();

    // warp tile: 32 rows x 64 cols
    int wm = (wid & 3) * 32;
    int wn = (wid >> 2) * 64;

    float acc[2][8][4];
    #pragma unroll
    for (int mi = 0; mi < 2; mi++)
        #pragma unroll
        for (int ni = 0; ni < 8; ni++)
            #pragma unroll
            for (int c = 0; c < 4; c++) acc[mi][ni][c] = 0.f;

    int lt = lane >> 3, lr = lane & 7;      // ldmatrix tile / row within tile
    int amr = lr + (lt & 1) * 8;            // m-row offset within 16
    int akc = (lt >> 1) * 8;                // k-col offset within 16

    #pragma unroll
    for (int kk = 0; kk < 8; kk++) {
        int k16 = kk * 16;
        uint32_t afrag[2][4];
        #pragma unroll
        for (int mi = 0; mi < 2; mi++) {
            uint32_t addr = sbA +
                ((wm + mi * 16 + amr) * ASTRIDE + k16 + akc) * 2;
            ldm_x4(afrag[mi], addr);
        }
        uint32_t bfrag[4][4];   // [n16 group][4 regs: (k0,n0),(k8,n0),(k0,n8),(k8,n8)]
        #pragma unroll
        for (int ng = 0; ng < 4; ng++) {
            uint32_t addr = sbB +
                ((k16 + amr) * ASTRIDE + wn + ng * 16 + akc) * 2;
            ldm_x4_t(bfrag[ng], addr);
        }
        #pragma unroll
        for (int mi = 0; mi < 2; mi++)
            #pragma unroll
            for (int ni = 0; ni < 8; ni++)
                mma16816(acc[mi][ni], afrag[mi], bfrag[ni >> 1] + (ni & 1) * 2);
    }

    // epilogue: scale by dis[row], pack half2, store to g_hs
    int qrow = lane >> 2;          // 0..7
    int qcol = lane & 3;           // half2 slot within 8 cols
    #pragma unroll
    for (int mi = 0; mi < 2; mi++) {
        #pragma unroll
        for (int half = 0; half < 2; half++) {   // c0c1 (row) / c2c3 (row+8)
            int rowG = rowBase + wm + mi * 16 + qrow + half * 8;
            if (rowG < N) {
                float s = g_dis[rowG];
                __half2* dst = g_hs + (size_t)rowG * 64 + wn / 2 + qcol;
                #pragma unroll
                for (int ni = 0; ni < 8; ni++) {
                    float c0 = acc[mi][ni][half * 2 + 0] * s;
                    float c1 = acc[mi][ni][half * 2 + 1] * s;
                    dst[ni * 4] = __float22half2_rn(make_float2(c0, c1));
                }
            }
        }
    }
}

// ---------------- gather + finalize ----------------
__global__ __launch_bounds__(256) void k_gather(
    float* __restrict__ out_ext, const float* __restrict__ bias,
    int N, int useExt)
{
    int node = blockIdx.x * 8 + (threadIdx.x >> 5);
    if (node >= N) return;
    int lane = threadIdx.x & 31;

    uint2 u = *(const uint2*)(g_hs + (size_t)node * 64 + lane * 2);
    float2 f0 = __half22float2(u32_to_h2(u.x));
    float2 f1 = __half22float2(u32_to_h2(u.y));
    float4 acc = make_float4(f0.x, f0.y, f1.x, f1.y);

    int beg = g_off[node], end = g_off[node + 1];
    for (int base = beg; base < end; base += 32) {
        int n = end - base; if (n > 32) n = 32;
        int eid = (lane < n) ? g_csr[base + lane] : 0;
        #pragma unroll 8
        for (int j = 0; j < n; j++) {
            int s = __shfl_sync(0xffffffffu, eid, j);
            uint2 v = __ldg((const uint2*)(g_hs + (size_t)s * 64 + lane * 2));
            float2 a = __half22float2(u32_to_h2(v.x));
            float2 b = __half22float2(u32_to_h2(v.y));
            acc.x += a.x; acc.y += a.y; acc.z += b.x; acc.w += b.y;
        }
    }

    float dn = g_dis[node];
    float4 bb = __ldg((const float4*)(bias + lane * 4));
    float4 r;
    r.x = fmaxf(fmaf(dn, acc.x, bb.x), 0.f);
    r.y = fmaxf(fmaf(dn, acc.y, bb.y), 0.f);
    r.z = fmaxf(fmaf(dn, acc.z, bb.z), 0.f);
    r.w = fmaxf(fmaf(dn, acc.w, bb.w), 0.f);

    float* __restrict__ out = useExt ? out_ext : g_act;
    *(float4*)(out + (size_t)node * HDIM + lane * 4) = r;
}

extern "C" void kernel_launch(void* const* d_in, const int* in_sizes, int n_in,
                              void* d_out, int out_size)
{
    const float* x  = (const float*)d_in[0];
    const void*  ei = d_in[1];
    const float* W1 = (const float*)d_in[2];
    const float* b1 = (const float*)d_in[3];
    const float* W2 = (const float*)d_in[4];
    const float* b2 = (const float*)d_in[5];

    int H = in_sizes[3];
    int D = in_sizes[2] / H;
    int N = in_sizes[0] / D;
    int E = in_sizes[1] / 2;
    (void)D; (void)n_in; (void)out_size;

    static bool attrDone = false;
    if (!attrDone) {
        cudaFuncSetAttribute(k_gemm_mma,
            cudaFuncAttributeMaxDynamicSharedMemorySize, SM_BYTES);
        attrDone = true;
    }

    int nb    = (N + 1023) / 1024;
    int eb    = (E + 255) / 256;
    int nb256 = (N + 255) / 256;
    int gemmBlocks = (N + 127) / 128;
    int gathBlocks = (N + 7) / 8;

    // setup + CSR build + weight conversion
    k_setup0<<<nb256, 256>>>(ei, E, N);
    k_convW<<<(2 * HDIM * 64 + 255) / 256, 256>>>(W1, W2);
    k_count<<<eb, 256>>>(ei, E, N);
    k_scan1<<<nb, 256>>>(N);
    k_scan23<<<nb256, 256>>>(N, E);
    k_fill<<<eb, 256>>>(ei, E, N);

    // layer 1
    k_gemm_mma<<<gemmBlocks, 256, SM_BYTES>>>(x, N, 0);
    k_gather<<<gathBlocks, 256>>>(nullptr, b1, N, 0);

    // layer 2
    k_gemm_mma<<<gemmBlocks, 256, SM_BYTES>>>(nullptr, N, 1);
    k_gather<<<gathBlocks, 256>>>((float*)d_out, b2, N, 1);
}